// round 12
// baseline (speedup 1.0000x reference)
#include <cuda_runtime.h>
#include <cuda_bf16.h>
#include <cstdint>

// STFT (real part only): n_fft=7, hop=2, win_len=6 (w_pad[6]=0), onesided n_freq=4.
// ABI ground truth (rounds 9-11):
//   d_in[0] = x, 32,000,000 float32  ([64, 500000])
//   d_in[1] = w, 6 float32
//   d_out   = 63,999,232 float32 (= 64*4*249997) -- harness casts the complex64
//             reference to float32, which keeps the REAL part.
// out[b][k][f] = sum_{n=0..5} x[b,2f+n]*w[n]*cos(2*pi*n*k/7)

namespace {

constexpr int NFREQ = 4;
constexpr int Bc    = 64;
constexpr int FPT   = 4;     // frames per thread
constexpr int TPB   = 256;

__global__ __launch_bounds__(TPB)
void stft_re_kernel(const float* __restrict__ x,
                    const float* __restrict__ w,
                    float* __restrict__ out,
                    long L, int F, long fcap)   // fcap: writable float elements
{
    // cos(2*pi*(n*k mod 7)/7) for k=1..3, n=1..5 (n=0 -> 1; n=6 unused).
    const float C1[5] = { 0.623489802f, -0.222520934f, -0.900968868f, -0.900968868f, -0.222520934f };
    const float C2[5] = {-0.222520934f, -0.900968868f,  0.623489802f,  0.623489802f, -0.900968868f };
    const float C3[5] = {-0.900968868f,  0.623489802f, -0.222520934f, -0.222520934f,  0.623489802f };

    const int chunk = blockIdx.x * TPB + threadIdx.x;
    const int b     = blockIdx.y;
    const int f0    = chunk * FPT;
    if (f0 >= F) return;

    float wv[6];
    #pragma unroll
    for (int n = 0; n < 6; n++) wv[n] = w[n];

    const float* xb = x + (size_t)b * (size_t)L;
    const long   s0 = 2L * (long)f0;
    const int    nf = min(FPT, F - f0);

    float s[12];
    const float* p32 = xb + s0;
    const bool vec_ok = (nf == FPT) && (s0 + 11 < L) &&
                        ((((uintptr_t)p32) & 15u) == 0);
    if (vec_ok) {
        const float4* p = reinterpret_cast<const float4*>(p32);
        float4 v0 = p[0], v1 = p[1], v2 = p[2];
        s[0]=v0.x; s[1]=v0.y; s[2]=v0.z;  s[3]=v0.w;
        s[4]=v1.x; s[5]=v1.y; s[6]=v1.z;  s[7]=v1.w;
        s[8]=v2.x; s[9]=v2.y; s[10]=v2.z; s[11]=v2.w;
    } else {
        #pragma unroll
        for (int i = 0; i < 12; i++) {
            long idx = s0 + i;
            s[i] = (idx < L) ? xb[idx] : 0.0f;
        }
    }

    float r0[FPT], r1[FPT], r2[FPT], r3[FPT];
    #pragma unroll
    for (int j = 0; j < FPT; j++) {
        float y[6];
        #pragma unroll
        for (int n = 0; n < 6; n++) y[n] = s[2*j + n] * wv[n];

        r0[j] = ((y[0] + y[1]) + (y[2] + y[3])) + (y[4] + y[5]);
        float a1 = y[0], a2 = y[0], a3 = y[0];
        #pragma unroll
        for (int n = 1; n < 6; n++) {
            a1 = fmaf(y[n], C1[n-1], a1);
            a2 = fmaf(y[n], C2[n-1], a2);
            a3 = fmaf(y[n], C3[n-1], a3);
        }
        r1[j] = a1; r2[j] = a2; r3[j] = a3;
    }

    // Float stores: per plane, 4 consecutive floats per thread; consecutive
    // threads contiguous -> full 32B sectors. Guarded by fcap.
    const long base = (long)b * NFREQ * (long)F + (long)f0;
    const long Fs   = (long)F;
    #pragma unroll
    for (int j = 0; j < FPT; j++) { long i = base + 0*Fs + j; if (j < nf && i < fcap) out[i] = r0[j]; }
    #pragma unroll
    for (int j = 0; j < FPT; j++) { long i = base + 1*Fs + j; if (j < nf && i < fcap) out[i] = r1[j]; }
    #pragma unroll
    for (int j = 0; j < FPT; j++) { long i = base + 2*Fs + j; if (j < nf && i < fcap) out[i] = r2[j]; }
    #pragma unroll
    for (int j = 0; j < FPT; j++) { long i = base + 3*Fs + j; if (j < nf && i < fcap) out[i] = r3[j]; }
}

} // namespace

extern "C" void kernel_launch(void* const* d_in, const int* in_sizes, int n_in,
                              void* d_out, int out_size)
{
    const float* x = (const float*)d_in[0];   // [64, 500000] float32
    const float* w = (const float*)d_in[1];   // [6] float32
    float* out     = (float*)d_out;           // [64, 4, 249997] float32 (real part)

    const long nx   = (long)in_sizes[0];             // 32,000,000
    const long L    = nx / Bc;                        // 500,000
    const int  F    = (int)(1 + (L - 7) / 2);         // 249,997
    const long fcap = (long)out_size;                 // 63,999,232 floats

    const int chunks = (F + FPT - 1) / FPT;                  // 62,500
    dim3 grid((unsigned)((chunks + TPB - 1) / TPB), Bc);     // (245, 64)
    stft_re_kernel<<<grid, TPB>>>(x, w, out, L, F, fcap);
}

// round 13
// speedup vs baseline: 1.1401x; 1.1401x over previous
#include <cuda_runtime.h>
#include <cuda_bf16.h>
#include <cstdint>

// STFT (real part only): n_fft=7, hop=2, win_len=6 (w_pad[6]=0), onesided n_freq=4.
// ABI ground truth (rounds 9-12):
//   d_in[0] = x, 32,000,000 float32  ([64, 500000])
//   d_in[1] = w, 6 float32
//   d_out   = 63,999,232 float32 ([64,4,249997]) -- real part of the STFT.
// out[b][k][f] = sum_{n=0..5} x[b,2f+n]*w[n]*cos(2*pi*n*k/7)
//
// R13: store-coalescing fix. Thread tid handles frames blockF0 + 256*j + tid
// (j=0..3), so every warp STG.32 writes 32 consecutive floats (minimal
// sectors) instead of the old stride-16B pattern (4x wavefront cost, seen as
// L1=71.8% in the r12 profile). Loads are lane-consecutive float2 slot reads.

namespace {

constexpr int NFREQ = 4;
constexpr int Bc    = 64;
constexpr int FPT   = 4;               // frames per thread
constexpr int TPB   = 256;
constexpr int TILE  = TPB * FPT;       // 1024 frames per block

__global__ __launch_bounds__(TPB)
void stft_re_kernel(const float* __restrict__ x,
                    const float* __restrict__ w,
                    float* __restrict__ out,
                    long L, int F, long fcap)
{
    // cos(2*pi*(n*k mod 7)/7) for k=1..3, n=1..5 (n=0 -> 1; n=6 unused).
    const float C1[5] = { 0.623489802f, -0.222520934f, -0.900968868f, -0.900968868f, -0.222520934f };
    const float C2[5] = {-0.222520934f, -0.900968868f,  0.623489802f,  0.623489802f, -0.900968868f };
    const float C3[5] = {-0.900968868f,  0.623489802f, -0.222520934f, -0.222520934f,  0.623489802f };

    const int tid     = threadIdx.x;
    const int b       = blockIdx.y;
    const int blockF0 = blockIdx.x * TILE;

    float wv[6];
    #pragma unroll
    for (int n = 0; n < 6; n++) wv[n] = w[n];

    // x row as float2 slots: slot f = { x[2f], x[2f+1] }. Row base is
    // b*500000*4B = b*2,000,000B -> 8B aligned.
    const float2* X2 = reinterpret_cast<const float2*>(x + (size_t)b * (size_t)L);

    const long obase = (long)b * NFREQ * (long)F;
    const long Fs    = (long)F;

    #pragma unroll
    for (int j = 0; j < FPT; j++) {
        const int f = blockF0 + j * TPB + tid;   // warp-consecutive frames
        if (f >= F) continue;

        // 6 samples x[2f..2f+5] = float2 slots f, f+1, f+2.
        // Max touched float: 2(F-1)+5 = 499997 < L -> always in bounds.
        const float2 a = __ldg(X2 + f);
        const float2 c = __ldg(X2 + f + 1);
        const float2 e = __ldg(X2 + f + 2);

        const float y0 = a.x * wv[0];
        const float y1 = a.y * wv[1];
        const float y2 = c.x * wv[2];
        const float y3 = c.y * wv[3];
        const float y4 = e.x * wv[4];
        const float y5 = e.y * wv[5];

        const float r0 = ((y0 + y1) + (y2 + y3)) + (y4 + y5);

        float r1 = y0, r2 = y0, r3 = y0;
        r1 = fmaf(y1, C1[0], r1);  r2 = fmaf(y1, C2[0], r2);  r3 = fmaf(y1, C3[0], r3);
        r1 = fmaf(y2, C1[1], r1);  r2 = fmaf(y2, C2[1], r2);  r3 = fmaf(y2, C3[1], r3);
        r1 = fmaf(y3, C1[2], r1);  r2 = fmaf(y3, C2[2], r2);  r3 = fmaf(y3, C3[2], r3);
        r1 = fmaf(y4, C1[3], r1);  r2 = fmaf(y4, C2[3], r2);  r3 = fmaf(y4, C3[3], r3);
        r1 = fmaf(y5, C1[4], r1);  r2 = fmaf(y5, C2[4], r2);  r3 = fmaf(y5, C3[4], r3);

        // Warp-coalesced scalar stores: lane-consecutive addresses per plane.
        const long i0 = obase + 0*Fs + f;
        const long i1 = obase + 1*Fs + f;
        const long i2 = obase + 2*Fs + f;
        const long i3 = obase + 3*Fs + f;
        if (i0 < fcap) out[i0] = r0;
        if (i1 < fcap) out[i1] = r1;
        if (i2 < fcap) out[i2] = r2;
        if (i3 < fcap) out[i3] = r3;
    }
}

} // namespace

extern "C" void kernel_launch(void* const* d_in, const int* in_sizes, int n_in,
                              void* d_out, int out_size)
{
    const float* x = (const float*)d_in[0];   // [64, 500000] float32
    const float* w = (const float*)d_in[1];   // [6] float32
    float* out     = (float*)d_out;           // [64, 4, 249997] float32 (real part)

    const long nx   = (long)in_sizes[0];             // 32,000,000
    const long L    = nx / Bc;                        // 500,000
    const int  F    = (int)(1 + (L - 7) / 2);         // 249,997
    const long fcap = (long)out_size;                 // 63,999,232 floats

    const int blocks_x = (F + TILE - 1) / TILE;       // 245
    dim3 grid((unsigned)blocks_x, Bc);                // (245, 64)
    stft_re_kernel<<<grid, TPB>>>(x, w, out, L, F, fcap);
}

// round 14
// speedup vs baseline: 1.2430x; 1.0903x over previous
#include <cuda_runtime.h>
#include <cuda_bf16.h>
#include <cstdint>

// STFT (real part only): n_fft=7, hop=2, win_len=6 (w_pad[6]=0), onesided n_freq=4.
// ABI ground truth (rounds 9-13):
//   d_in[0] = x, 32,000,000 float32  ([64, 500000])
//   d_in[1] = w, 6 float32
//   d_out   = 63,999,232 float32 ([64,4,249997]) -- real part of the STFT.
// out[b][k][f] = sum_{n=0..5} x[b,2f+n]*w[n]*cos(2*pi*n*k/7)
//
// R14: instruction-diet round. 32-bit offsets off a per-row 64-bit base,
// guard-free fast path for full tiles (out_size == 256*F validated on host),
// __stcs streaming stores (results never re-read). Store coalescing mapping
// from R13 kept: thread tid handles frames F0 + j*256 + tid.

namespace {

constexpr int NFREQ = 4;
constexpr int Bc    = 64;
constexpr int FPT   = 4;               // frames per thread
constexpr int TPB   = 256;
constexpr int TILE  = TPB * FPT;       // 1024 frames per block

__global__ __launch_bounds__(TPB)
void stft_re_kernel(const float* __restrict__ x,
                    const float* __restrict__ w,
                    float* __restrict__ out,
                    int L, int F,
                    int fullF,     // == F when geometry exact (enables fast path), else 0
                    int fcap)      // float store cap for guarded path
{
    // cos(2*pi*(n*k mod 7)/7) for k=1..3, n=1..5 (n=0 -> 1; n=6 unused).
    const float C1[5] = { 0.623489802f, -0.222520934f, -0.900968868f, -0.900968868f, -0.222520934f };
    const float C2[5] = {-0.222520934f, -0.900968868f,  0.623489802f,  0.623489802f, -0.900968868f };
    const float C3[5] = {-0.900968868f,  0.623489802f, -0.222520934f, -0.222520934f,  0.623489802f };

    const int tid = threadIdx.x;
    const int b   = blockIdx.y;
    const int F0  = blockIdx.x * TILE;

    float wv[6];
    #pragma unroll
    for (int n = 0; n < 6; n++) wv[n] = w[n];

    // Row bases (64-bit once; all per-frame offsets are 32-bit).
    const float2* __restrict__ X2 = reinterpret_cast<const float2*>(x) + (size_t)b * (size_t)(L >> 1);
    float* __restrict__ ob        = out + (size_t)b * (size_t)(NFREQ * F);

    if (F0 + TILE <= fullF) {
        // ---- fast path: no guards anywhere ----
        #pragma unroll
        for (int j = 0; j < FPT; j++) {
            const int f = F0 + j * TPB + tid;        // warp-consecutive frames

            const float2 a = __ldg(X2 + f);
            const float2 c = __ldg(X2 + f + 1);
            const float2 e = __ldg(X2 + f + 2);

            const float y0 = a.x * wv[0];
            const float y1 = a.y * wv[1];
            const float y2 = c.x * wv[2];
            const float y3 = c.y * wv[3];
            const float y4 = e.x * wv[4];
            const float y5 = e.y * wv[5];

            const float r0 = ((y0 + y1) + (y2 + y3)) + (y4 + y5);
            float r1 = y0, r2 = y0, r3 = y0;
            r1 = fmaf(y1, C1[0], r1);  r2 = fmaf(y1, C2[0], r2);  r3 = fmaf(y1, C3[0], r3);
            r1 = fmaf(y2, C1[1], r1);  r2 = fmaf(y2, C2[1], r2);  r3 = fmaf(y2, C3[1], r3);
            r1 = fmaf(y3, C1[2], r1);  r2 = fmaf(y3, C2[2], r2);  r3 = fmaf(y3, C3[2], r3);
            r1 = fmaf(y4, C1[3], r1);  r2 = fmaf(y4, C2[3], r2);  r3 = fmaf(y4, C3[3], r3);
            r1 = fmaf(y5, C1[4], r1);  r2 = fmaf(y5, C2[4], r2);  r3 = fmaf(y5, C3[4], r3);

            float* p = ob + f;
            __stcs(p, r0);  p += F;
            __stcs(p, r1);  p += F;
            __stcs(p, r2);  p += F;
            __stcs(p, r3);
        }
    } else {
        // ---- guarded path (tail block; also whole grid if ABI mismatch) ----
        #pragma unroll
        for (int j = 0; j < FPT; j++) {
            const int f = F0 + j * TPB + tid;
            if (f >= F) continue;

            const float2 a = __ldg(X2 + f);
            const float2 c = __ldg(X2 + f + 1);   // floats 2f+2..2f+3 <= 499995 < L
            const float2 e = __ldg(X2 + f + 2);   // floats 2f+4..2f+5 <= 499997 < L

            const float y0 = a.x * wv[0];
            const float y1 = a.y * wv[1];
            const float y2 = c.x * wv[2];
            const float y3 = c.y * wv[3];
            const float y4 = e.x * wv[4];
            const float y5 = e.y * wv[5];

            const float r0 = ((y0 + y1) + (y2 + y3)) + (y4 + y5);
            float r1 = y0, r2 = y0, r3 = y0;
            r1 = fmaf(y1, C1[0], r1);  r2 = fmaf(y1, C2[0], r2);  r3 = fmaf(y1, C3[0], r3);
            r1 = fmaf(y2, C1[1], r1);  r2 = fmaf(y2, C2[1], r2);  r3 = fmaf(y2, C3[1], r3);
            r1 = fmaf(y3, C1[2], r1);  r2 = fmaf(y3, C2[2], r2);  r3 = fmaf(y3, C3[2], r3);
            r1 = fmaf(y4, C1[3], r1);  r2 = fmaf(y4, C2[3], r2);  r3 = fmaf(y4, C3[3], r3);
            r1 = fmaf(y5, C1[4], r1);  r2 = fmaf(y5, C2[4], r2);  r3 = fmaf(y5, C3[4], r3);

            const long gbase = (long)b * (long)(NFREQ * F) + f;   // for fcap guard
            if (gbase + 0L*F < (long)fcap) __stcs(ob + f,         r0);
            if (gbase + 1L*F < (long)fcap) __stcs(ob + F + f,     r1);
            if (gbase + 2L*F < (long)fcap) __stcs(ob + 2*F + f,   r2);
            if (gbase + 3L*F < (long)fcap) __stcs(ob + 3*F + f,   r3);
        }
    }
}

} // namespace

extern "C" void kernel_launch(void* const* d_in, const int* in_sizes, int n_in,
                              void* d_out, int out_size)
{
    const float* x = (const float*)d_in[0];   // [64, 500000] float32
    const float* w = (const float*)d_in[1];   // [6] float32
    float* out     = (float*)d_out;           // [64, 4, 249997] float32 (real part)

    const long nx = (long)in_sizes[0];              // 32,000,000
    const int  L  = (int)(nx / Bc);                  // 500,000
    const int  F  = 1 + (L - 7) / 2;                 // 249,997

    // Fast path only when the output geometry is exactly what we derived.
    const bool exact = ((long)out_size == (long)NFREQ * Bc * (long)F);
    const int  fullF = exact ? F : 0;

    const int blocks_x = (F + TILE - 1) / TILE;      // 245
    dim3 grid((unsigned)blocks_x, Bc);               // (245, 64)
    stft_re_kernel<<<grid, TPB>>>(x, w, out, L, F, fullF, out_size);
}